// round 15
// baseline (speedup 1.0000x reference)
#include <cuda_runtime.h>
#include <cuda_bf16.h>
#include <cstdint>

#define D      128
#define NROW   50000
#define NCOL   50000
#define NTOT   (NROW + NCOL)
#define BM     64

// X tile: 64 rows x 128 k bf16, row stride 272B
#define LDB_B   272
#define XTILE_B (64 * LDB_B)          // 17408
// W half-tile: 128 n-rows x 64 k bf16, row stride 144B
#define LDW_B   144
#define WHALF_B (128 * LDW_B)         // 18432
#define WHALF_U4 (WHALF_B / 16)       // 1152

// Scratch (alloc-free rule: __device__ globals)
__device__ float g_agg1[(size_t)NROW * D];
__device__ float g_agg2[(size_t)NCOL * D];
__device__ float g_hrow[(size_t)NROW * D];
__device__ uint4 g_wt[4][2][2][WHALF_U4];   // [matrix][khalf][hi/lo]
__device__ int   g_cnt[NTOT];
__device__ int   g_ptr[NTOT + 1];
__device__ int   g_cur[NTOT];
__device__ int   g_bsum[128];
__device__ int   g_flag;
__device__ int2  g_edges[1200000];

__device__ __forceinline__ float leaky(float v) { return v >= 0.f ? v : 0.01f * v; }

// ---------------- weight pre-split + counter zero (merged prep) ----------------
static __device__ __forceinline__ void split8(const float* x, uint32_t* hi, uint32_t* lo) {
    #pragma unroll
    for (int j = 0; j < 4; j++) {
        __nv_bfloat16 h0 = __float2bfloat16(x[2*j]);
        __nv_bfloat16 h1 = __float2bfloat16(x[2*j+1]);
        __nv_bfloat16 l0 = __float2bfloat16(x[2*j]   - __bfloat162float(h0));
        __nv_bfloat16 l1 = __float2bfloat16(x[2*j+1] - __bfloat162float(h1));
        hi[j] = (uint32_t)__bfloat16_as_ushort(h0) | ((uint32_t)__bfloat16_as_ushort(h1) << 16);
        lo[j] = (uint32_t)__bfloat16_as_ushort(l0) | ((uint32_t)__bfloat16_as_ushort(l1) << 16);
    }
}

static __device__ __forceinline__ void split2(float x0, float x1, uint32_t& hi, uint32_t& lo) {
    __nv_bfloat16 h0 = __float2bfloat16(x0);
    __nv_bfloat16 h1 = __float2bfloat16(x1);
    __nv_bfloat16 l0 = __float2bfloat16(x0 - __bfloat162float(h0));
    __nv_bfloat16 l1 = __float2bfloat16(x1 - __bfloat162float(h1));
    hi = (uint32_t)__bfloat16_as_ushort(h0) | ((uint32_t)__bfloat16_as_ushort(h1) << 16);
    lo = (uint32_t)__bfloat16_as_ushort(l0) | ((uint32_t)__bfloat16_as_ushort(l1) << 16);
}

__global__ void prep_kernel(const float* __restrict__ Wa, const float* __restrict__ Wb,
                            const float* __restrict__ Wc, const float* __restrict__ Wd,
                            int* __restrict__ cnt, int* __restrict__ flag) {
    int task = blockIdx.x * blockDim.x + threadIdx.x;   // 0..8191
    for (int i = task; i < NTOT; i += 8192) cnt[i] = 0;
    if (task == 0) *flag = 0;
    int m = task >> 11;
    int tt = task & 2047;
    int n = tt & 127, kg = tt >> 7;
    const float* W = (m == 0) ? Wa : (m == 1) ? Wb : (m == 2) ? Wc : Wd;
    float v[8];
    #pragma unroll
    for (int j = 0; j < 8; j++) v[j] = __ldg(W + (kg * 8 + j) * D + n);
    uint32_t hi[4], lo[4];
    split8(v, hi, lo);
    int half = kg >> 3, kgl = kg & 7;
    int idx = n * 9 + kgl;
    g_wt[m][half][0][idx] = make_uint4(hi[0], hi[1], hi[2], hi[3]);
    g_wt[m][half][1][idx] = make_uint4(lo[0], lo[1], lo[2], lo[3]);
}

// ---------------- CSR build ----------------
__global__ void hist2_kernel(const int* __restrict__ dst1, const int* __restrict__ dst2,
                             int* __restrict__ cnt, int E) {
    int e = blockIdx.x * blockDim.x + threadIdx.x;
    if (e >= 2 * E) return;
    if (e < E) atomicAdd(cnt + __ldg(dst1 + e), 1);
    else       atomicAdd(cnt + NROW + __ldg(dst2 + e - E), 1);
}

// block-local exclusive scan + block totals; LAST block also scans the totals.
__global__ void scan_blk_kernel(const int* __restrict__ cnt, int* __restrict__ ptr,
                                int* __restrict__ bsum, int* __restrict__ flag, int n) {
    __shared__ int wsum[32];
    __shared__ int tmp[128];
    __shared__ int is_last;
    int tid = threadIdx.x, lane = tid & 31, wid = tid >> 5;
    int i = blockIdx.x * 1024 + tid;
    int x = (i < n) ? cnt[i] : 0;
    int v = x;
    #pragma unroll
    for (int o = 1; o < 32; o <<= 1) { int t = __shfl_up_sync(~0u, v, o); if (lane >= o) v += t; }
    if (lane == 31) wsum[wid] = v;
    __syncthreads();
    if (wid == 0) {
        int s = wsum[lane];
        #pragma unroll
        for (int o = 1; o < 32; o <<= 1) { int t = __shfl_up_sync(~0u, s, o); if (lane >= o) s += t; }
        wsum[lane] = s;
    }
    __syncthreads();
    int woff = wid ? wsum[wid - 1] : 0;
    if (i < n) ptr[i] = woff + v - x;

    if (tid == 0) {
        bsum[blockIdx.x] = wsum[31];
        __threadfence();
        int old = atomicAdd(flag, 1);
        is_last = (old == (int)gridDim.x - 1) ? 1 : 0;
    }
    __syncthreads();
    if (is_last) {
        __threadfence();
        int nb = gridDim.x;                 // <= 128
        int xx = (tid < nb) ? bsum[tid] : 0;
        if (tid < 128) tmp[tid] = xx;
        __syncthreads();
        for (int o = 1; o < 128; o <<= 1) {
            int t = (tid >= o && tid < 128) ? tmp[tid - o] : 0;
            __syncthreads();
            if (tid < 128) tmp[tid] += t;
            __syncthreads();
        }
        if (tid < nb) bsum[tid] = tmp[tid] - xx;
    }
}

__global__ void scan_add_kernel(int* __restrict__ ptr, int* __restrict__ cur,
                                const int* __restrict__ bsum, int n, int total) {
    int i = blockIdx.x * blockDim.x + threadIdx.x;
    if (i < n) {
        int v = ptr[i] + bsum[i >> 10];
        ptr[i] = v;
        cur[i] = v;
    }
    if (i == 0) ptr[n] = total;
}

__global__ void scatter2_kernel(const int* __restrict__ src1, const int* __restrict__ dst1,
                                const float* __restrict__ w1,
                                const int* __restrict__ src2, const int* __restrict__ dst2,
                                const float* __restrict__ w2,
                                int* __restrict__ cur, int2* __restrict__ edges, int E) {
    int e = blockIdx.x * blockDim.x + threadIdx.x;
    if (e >= 2 * E) return;
    if (e < E) {
        int pos = atomicAdd(cur + __ldg(dst1 + e), 1);
        edges[pos] = make_int2(__ldg(src1 + e), __float_as_int(__ldg(w1 + e)));
    } else {
        int ee = e - E;
        int pos = atomicAdd(cur + NROW + __ldg(dst2 + ee), 1);
        edges[pos] = make_int2(__ldg(src2 + ee), __float_as_int(__ldg(w2 + ee)));
    }
}

// ---------------- CSR aggregation: TWO nodes per warp, 16 lanes each ----------------
// Each lane covers 32B (two float4) of its node's 512B row -> 4 independent
// gather loads per lane per 2-edge iteration (2x MLP of the 1-node/warp version).
__global__ void csr_agg_kernel(const float4* __restrict__ feat,
                               const int* __restrict__ ptr,
                               const int2* __restrict__ edges,
                               float* __restrict__ agg, int n, int off) {
    int t = blockIdx.x * blockDim.x + threadIdx.x;
    int wpair = t >> 5;
    int lane = t & 31;
    int node = wpair * 2 + (lane >> 4);
    int l = lane & 15;
    if (node >= n) return;
    int beg = __ldg(ptr + off + node);
    int end = __ldg(ptr + off + node + 1);
    float4 a0 = make_float4(0.f, 0.f, 0.f, 0.f);
    float4 a1 = make_float4(0.f, 0.f, 0.f, 0.f);
    float4 b0 = make_float4(0.f, 0.f, 0.f, 0.f);
    float4 b1 = make_float4(0.f, 0.f, 0.f, 0.f);
    int i = beg;
    for (; i + 2 <= end; i += 2) {
        int2 e0 = __ldg(edges + i);
        int2 e1 = __ldg(edges + i + 1);
        float w0 = __int_as_float(e0.y), w1 = __int_as_float(e1.y);
        const float4* r0 = feat + (size_t)e0.x * 32 + l * 2;
        const float4* r1 = feat + (size_t)e1.x * 32 + l * 2;
        float4 v00 = __ldg(r0);
        float4 v01 = __ldg(r0 + 1);
        float4 v10 = __ldg(r1);
        float4 v11 = __ldg(r1 + 1);
        a0.x = fmaf(v00.x, w0, a0.x); a0.y = fmaf(v00.y, w0, a0.y);
        a0.z = fmaf(v00.z, w0, a0.z); a0.w = fmaf(v00.w, w0, a0.w);
        a1.x = fmaf(v01.x, w0, a1.x); a1.y = fmaf(v01.y, w0, a1.y);
        a1.z = fmaf(v01.z, w0, a1.z); a1.w = fmaf(v01.w, w0, a1.w);
        b0.x = fmaf(v10.x, w1, b0.x); b0.y = fmaf(v10.y, w1, b0.y);
        b0.z = fmaf(v10.z, w1, b0.z); b0.w = fmaf(v10.w, w1, b0.w);
        b1.x = fmaf(v11.x, w1, b1.x); b1.y = fmaf(v11.y, w1, b1.y);
        b1.z = fmaf(v11.z, w1, b1.z); b1.w = fmaf(v11.w, w1, b1.w);
    }
    if (i < end) {
        int2 e0 = __ldg(edges + i);
        float w0 = __int_as_float(e0.y);
        const float4* r0 = feat + (size_t)e0.x * 32 + l * 2;
        float4 v00 = __ldg(r0);
        float4 v01 = __ldg(r0 + 1);
        a0.x = fmaf(v00.x, w0, a0.x); a0.y = fmaf(v00.y, w0, a0.y);
        a0.z = fmaf(v00.z, w0, a0.z); a0.w = fmaf(v00.w, w0, a0.w);
        a1.x = fmaf(v01.x, w0, a1.x); a1.y = fmaf(v01.y, w0, a1.y);
        a1.z = fmaf(v01.z, w0, a1.z); a1.w = fmaf(v01.w, w0, a1.w);
    }
    float4* o = (float4*)agg + (size_t)node * 32 + l * 2;
    o[0] = make_float4(a0.x + b0.x, a0.y + b0.y, a0.z + b0.z, a0.w + b0.w);
    o[1] = make_float4(a1.x + b1.x, a1.y + b1.y, a1.z + b1.z, a1.w + b1.w);
}

// ---------------- HMMA (mma.sync) MLP, pipelined W halves (R13 version) ----------------
#define SM_XHI  0
#define SM_XLO  (SM_XHI + XTILE_B)
#define SM_WS0  (SM_XLO + XTILE_B)
#define SM_WS1  (SM_WS0 + WHALF_B)
#define SM_WS2  (SM_WS1 + WHALF_B)
#define SM_WS3  (SM_WS2 + WHALF_B)
#define SM_B1   (SM_WS3 + WHALF_B)
#define SM_B2   (SM_B1 + 512)
#define SM_TOTAL (SM_B2 + 512)            // 109568 -> 2 CTAs/SM
#define SM_FST  SM_WS0
#define LDF     132

static __device__ __forceinline__ uint32_t smem_u32(const void* p) {
    uint32_t a;
    asm("{ .reg .u64 t; cvta.to.shared.u64 t, %1; cvt.u32.u64 %0, t; }" : "=r"(a) : "l"(p));
    return a;
}

static __device__ __forceinline__ void ldsm4(uint32_t* r, uint32_t addr) {
    asm volatile("ldmatrix.sync.aligned.m8n8.x4.shared.b16 {%0,%1,%2,%3}, [%4];"
                 : "=r"(r[0]), "=r"(r[1]), "=r"(r[2]), "=r"(r[3]) : "r"(addr));
}

static __device__ __forceinline__ void mma16816(float* d, const uint32_t* a,
                                                uint32_t b0, uint32_t b1) {
    asm volatile("mma.sync.aligned.m16n8k16.row.col.f32.bf16.bf16.f32 "
                 "{%0,%1,%2,%3}, {%4,%5,%6,%7}, {%8,%9}, {%0,%1,%2,%3};"
                 : "+f"(d[0]), "+f"(d[1]), "+f"(d[2]), "+f"(d[3])
                 : "r"(a[0]), "r"(a[1]), "r"(a[2]), "r"(a[3]), "r"(b0), "r"(b1));
}

static __device__ __forceinline__ void stage_whalf(uint32_t smb, uint32_t hi_off, uint32_t lo_off,
                                                   const uint4* __restrict__ half_base, int tid) {
    const uint4* hi = half_base;
    const uint4* lo = half_base + WHALF_U4;
    for (int i = tid; i < WHALF_U4; i += 256) {
        asm volatile("cp.async.cg.shared.global [%0], [%1], 16;"
                     :: "r"(smb + hi_off + (uint32_t)i * 16), "l"(hi + i));
        asm volatile("cp.async.cg.shared.global [%0], [%1], 16;"
                     :: "r"(smb + lo_off + (uint32_t)i * 16), "l"(lo + i));
    }
    asm volatile("cp.async.commit_group;" ::: "memory");
}
template <int N>
static __device__ __forceinline__ void wait_cp_n() {
    asm volatile("cp.async.wait_group %0;" :: "n"(N) : "memory");
}

// one k-half of a layer, 2x4 warp grid
static __device__ __forceinline__ void do_half(uint32_t smb, uint32_t whi, uint32_t wlo,
                                               int khalf, int mg, int ng, int lane,
                                               float acc[8][4]) {
    const int rsel = lane & 15;
    const uint32_t koff = (uint32_t)((lane >> 4) << 4);
    #pragma unroll
    for (int kk = 0; kk < 4; kk++) {
        uint32_t rowkA = (uint32_t)(khalf * 4 + kk) * 32 + koff;
        uint32_t rowkB = (uint32_t)kk * 32 + koff;
        uint32_t bh[2][4], bl[2][4];
        #pragma unroll
        for (int nb = 0; nb < 2; nb++) {
            uint32_t boff = (uint32_t)(ng * 32 + nb * 16 + rsel) * LDW_B + rowkB;
            ldsm4(bh[nb], smb + whi + boff);
            ldsm4(bl[nb], smb + wlo + boff);
        }
        #pragma unroll
        for (int mt = 0; mt < 2; mt++) {
            uint32_t aoff = (uint32_t)(mg * 32 + mt * 16 + rsel) * LDB_B + rowkA;
            uint32_t ahi[4], alo[4];
            ldsm4(ahi, smb + SM_XHI + aoff);
            ldsm4(alo, smb + SM_XLO + aoff);
            #pragma unroll
            for (int nb = 0; nb < 2; nb++) {
                float* d0 = acc[mt * 4 + nb * 2];
                float* d1 = acc[mt * 4 + nb * 2 + 1];
                mma16816(d0, ahi, bh[nb][0], bh[nb][2]);
                mma16816(d1, ahi, bh[nb][1], bh[nb][3]);
                mma16816(d0, ahi, bl[nb][0], bl[nb][2]);
                mma16816(d1, ahi, bl[nb][1], bl[nb][3]);
                mma16816(d0, alo, bh[nb][0], bh[nb][2]);
                mma16816(d1, alo, bh[nb][1], bh[nb][3]);
            }
        }
    }
}

__global__ void __launch_bounds__(256, 2)
mlp_tc_kernel(const float* __restrict__ feat, const float* __restrict__ agg,
              const uint4* __restrict__ wmat1, const uint4* __restrict__ wmat2,
              const float* __restrict__ b1, const float* __restrict__ b2,
              const float* __restrict__ eps_p,
              float* __restrict__ h_out, float* __restrict__ out, int N) {
    extern __shared__ char sm[];
    const uint32_t smb = smem_u32(sm);
    const int tid = threadIdx.x;
    const int wid = tid >> 5;
    const int lane = tid & 31;
    const int mg = wid & 1;            // 2 m-groups of 32 rows
    const int ng = wid >> 1;           // 4 n-groups of 32 cols
    const int row0 = blockIdx.x * BM;
    const float eps1 = 1.f + __ldg(eps_p);

    const float4* feat4 = (const float4*)feat;
    const float4* agg4  = (const float4*)agg;
    float* sB1 = (float*)(sm + SM_B1);
    float* sB2 = (float*)(sm + SM_B2);

    // prefetch W1 (both halves) under X staging
    stage_whalf(smb, SM_WS0, SM_WS1, wmat1, tid);                 // group: W1h1
    stage_whalf(smb, SM_WS2, SM_WS3, wmat1 + 2 * WHALF_U4, tid);  // group: W1h2

    if (tid < 128) {
        sB1[tid] = __ldg(b1 + tid);
        sB2[tid] = __ldg(b2 + tid);
    }

    // ---- stage x = (1+eps)*feat + agg as bf16 hi/lo (64 rows) ----
    #pragma unroll
    for (int i = 0; i < 4; i++) {
        int tt = tid + i * 256;
        int tr = tt >> 4, kg = tt & 15;
        int grow = row0 + tr;
        float v[8];
        if (grow < N) {
            float4 f0 = __ldg(feat4 + (size_t)grow * 32 + kg * 2);
            float4 f1 = __ldg(feat4 + (size_t)grow * 32 + kg * 2 + 1);
            float4 a0 = __ldg(agg4  + (size_t)grow * 32 + kg * 2);
            float4 a1 = __ldg(agg4  + (size_t)grow * 32 + kg * 2 + 1);
            v[0] = fmaf(eps1, f0.x, a0.x); v[1] = fmaf(eps1, f0.y, a0.y);
            v[2] = fmaf(eps1, f0.z, a0.z); v[3] = fmaf(eps1, f0.w, a0.w);
            v[4] = fmaf(eps1, f1.x, a1.x); v[5] = fmaf(eps1, f1.y, a1.y);
            v[6] = fmaf(eps1, f1.z, a1.z); v[7] = fmaf(eps1, f1.w, a1.w);
        } else {
            #pragma unroll
            for (int j = 0; j < 8; j++) v[j] = 0.f;
        }
        uint32_t hi[4], lo[4];
        split8(v, hi, lo);
        uint32_t off = (uint32_t)tr * LDB_B + (uint32_t)kg * 16;
        *(uint4*)(sm + SM_XHI + off) = make_uint4(hi[0], hi[1], hi[2], hi[3]);
        *(uint4*)(sm + SM_XLO + off) = make_uint4(lo[0], lo[1], lo[2], lo[3]);
    }

    float acc[8][4];
    #pragma unroll
    for (int t = 0; t < 8; t++)
        #pragma unroll
        for (int j = 0; j < 4; j++) acc[t][j] = 0.f;

    wait_cp_n<1>();          // W1h1 arrived
    __syncthreads();

    // ---- L1 half a (k 0..63) ----
    do_half(smb, SM_WS0, SM_WS1, 0, mg, ng, lane, acc);

    wait_cp_n<0>();          // W1h2 arrived
    __syncthreads();         // all warps done reading WS0/1
    stage_whalf(smb, SM_WS0, SM_WS1, wmat2, tid);   // W2h1 streams under L1b

    // ---- L1 half b (k 64..127) ----
    do_half(smb, SM_WS2, SM_WS3, 1, mg, ng, lane, acc);
    __syncthreads();         // all warps done reading X (and W1h2)

    // writeback h1 = leaky(acc + b1) into X tiles
    {
        const int c0 = 2 * (lane & 3);
        #pragma unroll
        for (int mt = 0; mt < 2; mt++) {
            const int r0 = mg * 32 + mt * 16 + (lane >> 2);
            #pragma unroll
            for (int nb = 0; nb < 2; nb++) {
                #pragma unroll
                for (int s = 0; s < 2; s++) {
                    int c = ng * 32 + nb * 16 + s * 8 + c0;
                    const float* a = acc[mt * 4 + nb * 2 + s];
                    float v0 = leaky(a[0] + sB1[c]);
                    float v1 = leaky(a[1] + sB1[c + 1]);
                    float v2 = leaky(a[2] + sB1[c]);
                    float v3 = leaky(a[3] + sB1[c + 1]);
                    uint32_t h01, l01, h23, l23;
                    split2(v0, v1, h01, l01);
                    split2(v2, v3, h23, l23);
                    uint32_t o0 = (uint32_t)r0 * LDB_B + (uint32_t)c * 2;
                    uint32_t o1 = o0 + 8u * LDB_B;
                    *(uint32_t*)(sm + SM_XHI + o0) = h01;
                    *(uint32_t*)(sm + SM_XLO + o0) = l01;
                    *(uint32_t*)(sm + SM_XHI + o1) = h23;
                    *(uint32_t*)(sm + SM_XLO + o1) = l23;
                }
            }
        }
    }

    #pragma unroll
    for (int t = 0; t < 8; t++)
        #pragma unroll
        for (int j = 0; j < 4; j++) acc[t][j] = 0.f;

    wait_cp_n<0>();          // W2h1 arrived
    __syncthreads();         // h1 writeback visible; W2h1 visible
    stage_whalf(smb, SM_WS2, SM_WS3, wmat2 + 2 * WHALF_U4, tid);  // W2h2 under L2a

    // ---- L2 half a ----
    do_half(smb, SM_WS0, SM_WS1, 0, mg, ng, lane, acc);

    wait_cp_n<0>();          // W2h2 arrived
    __syncthreads();
    // ---- L2 half b ----
    do_half(smb, SM_WS2, SM_WS3, 1, mg, ng, lane, acc);

    // epilogue staging (reuses WS0/1; all warps past L2a reads)
    __syncthreads();
    {
        float* fst = (float*)(sm + SM_FST);
        const int c0 = 2 * (lane & 3);
        #pragma unroll
        for (int mt = 0; mt < 2; mt++) {
            const int r0 = mg * 32 + mt * 16 + (lane >> 2);
            #pragma unroll
            for (int nb = 0; nb < 2; nb++) {
                #pragma unroll
                for (int s = 0; s < 2; s++) {
                    int c = ng * 32 + nb * 16 + s * 8 + c0;
                    const float* a = acc[mt * 4 + nb * 2 + s];
                    float v0 = leaky(a[0] + sB2[c]);
                    float v1 = leaky(a[1] + sB2[c + 1]);
                    float v2 = leaky(a[2] + sB2[c]);
                    float v3 = leaky(a[3] + sB2[c + 1]);
                    *(float2*)(fst + (size_t)r0 * LDF + c)       = make_float2(v0, v1);
                    *(float2*)(fst + (size_t)(r0 + 8) * LDF + c) = make_float2(v2, v3);
                }
            }
        }
    }
    __syncthreads();

    // coalesced final writes: out = h2 + feat; h_out = h2
    {
        const float* fst = (const float*)(sm + SM_FST);
        #pragma unroll
        for (int i = 0; i < 8; i++) {
            int idx = tid + i * 256;
            int r = idx >> 5, c4 = idx & 31;
            int grow = row0 + r;
            if (grow >= N) continue;
            const float* p = fst + (size_t)r * LDF + c4 * 4;
            float4 h = make_float4(p[0], p[1], p[2], p[3]);
            float4 fv = __ldg(feat4 + (size_t)grow * 32 + c4);
            ((float4*)out)[(size_t)grow * 32 + c4] =
                make_float4(h.x + fv.x, h.y + fv.y, h.z + fv.z, h.w + fv.w);
            if (h_out)
                ((float4*)h_out)[(size_t)grow * 32 + c4] = h;
        }
    }
}

extern "C" void kernel_launch(void* const* d_in, const int* in_sizes, int n_in,
                              void* d_out, int out_size) {
    const float* feat_row = (const float*)d_in[0];
    const float* feat_col = (const float*)d_in[1];
    const int*   src_c2r  = (const int*)d_in[2];
    const int*   dst_c2r  = (const int*)d_in[3];
    const float* w_c2r    = (const float*)d_in[4];
    const int*   src_r2c  = (const int*)d_in[5];
    const int*   dst_r2c  = (const int*)d_in[6];
    const float* w_r2c    = (const float*)d_in[7];
    const float* W1_c2r   = (const float*)d_in[8];
    const float* b1_c2r   = (const float*)d_in[9];
    const float* W2_c2r   = (const float*)d_in[10];
    const float* b2_c2r   = (const float*)d_in[11];
    const float* W1_r2c   = (const float*)d_in[12];
    const float* b1_r2c   = (const float*)d_in[13];
    const float* W2_r2c   = (const float*)d_in[14];
    const float* b2_r2c   = (const float*)d_in[15];
    const float* eps_c2r  = (const float*)d_in[16];
    const float* eps_r2c  = (const float*)d_in[17];

    const int E = in_sizes[2];

    float* out_row = (float*)d_out;
    float* out_col = out_row + (size_t)NROW * D;

    float *agg1, *agg2, *hrow;
    uint4* wt;
    int *cnt, *ptr, *cur, *bsum, *flag;
    int2* edges;
    cudaGetSymbolAddress((void**)&agg1,  g_agg1);
    cudaGetSymbolAddress((void**)&agg2,  g_agg2);
    cudaGetSymbolAddress((void**)&hrow,  g_hrow);
    cudaGetSymbolAddress((void**)&wt,    g_wt);
    cudaGetSymbolAddress((void**)&cnt,   g_cnt);
    cudaGetSymbolAddress((void**)&ptr,   g_ptr);
    cudaGetSymbolAddress((void**)&cur,   g_cur);
    cudaGetSymbolAddress((void**)&bsum,  g_bsum);
    cudaGetSymbolAddress((void**)&flag,  g_flag);
    cudaGetSymbolAddress((void**)&edges, g_edges);

    const int MAT_U4 = 2 * 2 * WHALF_U4;
    const uint4* w1_a = wt + 0 * MAT_U4;
    const uint4* w2_a = wt + 1 * MAT_U4;
    const uint4* w1_b = wt + 2 * MAT_U4;
    const uint4* w2_b = wt + 3 * MAT_U4;

    cudaFuncSetAttribute(mlp_tc_kernel, cudaFuncAttributeMaxDynamicSharedMemorySize, SM_TOTAL);

    const int e2grid = (2 * E + 255) / 256;
    const int g_row = (NROW + BM - 1) / BM;
    const int g_col = (NCOL + BM - 1) / BM;
    const int nscan_blocks = (NTOT + 1023) / 1024;
    const int agg_grid = (((NROW + 1) / 2) * 32 + 255) / 256;   // 2 nodes per warp

    // ---- CSR build (5 launches, R13 chain) ----
    prep_kernel<<<32, 256>>>(W1_c2r, W2_c2r, W1_r2c, W2_r2c, cnt, flag);
    hist2_kernel<<<e2grid, 256>>>(dst_c2r, dst_r2c, cnt, E);
    scan_blk_kernel<<<nscan_blocks, 1024>>>(cnt, ptr, bsum, flag, NTOT);
    scan_add_kernel<<<(NTOT + 255) / 256, 256>>>(ptr, cur, bsum, NTOT, 2 * E);
    scatter2_kernel<<<e2grid, 256>>>(src_c2r, dst_c2r, w_c2r, src_r2c, dst_r2c, w_r2c,
                                     cur, edges, E);

    // ---- col -> row ----
    csr_agg_kernel<<<agg_grid, 256>>>((const float4*)feat_col, ptr, edges, agg1, NROW, 0);
    mlp_tc_kernel<<<g_row, 256, SM_TOTAL>>>(feat_row, agg1, w1_a, w2_a,
                                            b1_c2r, b2_c2r, eps_c2r, hrow, out_row, NROW);
    // ---- row -> col (uses updated h_row) ----
    csr_agg_kernel<<<agg_grid, 256>>>((const float4*)hrow, ptr, edges, agg2, NCOL, NROW);
    mlp_tc_kernel<<<g_col, 256, SM_TOTAL>>>(feat_col, agg2, w1_b, w2_b,
                                            b1_r2c, b2_r2c, eps_r2c, nullptr, out_col, NCOL);
}

// round 16
// speedup vs baseline: 1.0430x; 1.0430x over previous
#include <cuda_runtime.h>
#include <cuda_bf16.h>
#include <cstdint>

#define D      128
#define NROW   50000
#define NCOL   50000
#define NTOT   (NROW + NCOL)
#define BM     64

// X tile: 64 rows x 128 k bf16, row stride 272B
#define LDB_B   272
#define XTILE_B (64 * LDB_B)          // 17408
// W half-tile: 128 n-rows x 64 k bf16, row stride 144B
#define LDW_B   144
#define WHALF_B (128 * LDW_B)         // 18432
#define WHALF_U4 (WHALF_B / 16)       // 1152

// Scratch (alloc-free rule: __device__ globals)
__device__ float g_agg1[(size_t)NROW * D];
__device__ float g_agg2[(size_t)NCOL * D];
__device__ float g_hrow[(size_t)NROW * D];
__device__ uint4 g_wt[4][2][2][WHALF_U4];   // [matrix][khalf][hi/lo]
__device__ int   g_cnt[NTOT];
__device__ int   g_ptr[NTOT + 2];           // ptr1[NROW+1] then ptr2[NCOL+1]
__device__ int   g_cur[NTOT];
__device__ int   g_bsum[128];               // [0:64) graph1, [64:128) graph2
__device__ int   g_flag[2];
__device__ int2  g_edges[1200000];

__device__ __forceinline__ float leaky(float v) { return v >= 0.f ? v : 0.01f * v; }

// ---------------- weight pre-split + counter/flag zero (merged prep) ----------------
static __device__ __forceinline__ void split8(const float* x, uint32_t* hi, uint32_t* lo) {
    #pragma unroll
    for (int j = 0; j < 4; j++) {
        __nv_bfloat16 h0 = __float2bfloat16(x[2*j]);
        __nv_bfloat16 h1 = __float2bfloat16(x[2*j+1]);
        __nv_bfloat16 l0 = __float2bfloat16(x[2*j]   - __bfloat162float(h0));
        __nv_bfloat16 l1 = __float2bfloat16(x[2*j+1] - __bfloat162float(h1));
        hi[j] = (uint32_t)__bfloat16_as_ushort(h0) | ((uint32_t)__bfloat16_as_ushort(h1) << 16);
        lo[j] = (uint32_t)__bfloat16_as_ushort(l0) | ((uint32_t)__bfloat16_as_ushort(l1) << 16);
    }
}

static __device__ __forceinline__ void split2(float x0, float x1, uint32_t& hi, uint32_t& lo) {
    __nv_bfloat16 h0 = __float2bfloat16(x0);
    __nv_bfloat16 h1 = __float2bfloat16(x1);
    __nv_bfloat16 l0 = __float2bfloat16(x0 - __bfloat162float(h0));
    __nv_bfloat16 l1 = __float2bfloat16(x1 - __bfloat162float(h1));
    hi = (uint32_t)__bfloat16_as_ushort(h0) | ((uint32_t)__bfloat16_as_ushort(h1) << 16);
    lo = (uint32_t)__bfloat16_as_ushort(l0) | ((uint32_t)__bfloat16_as_ushort(l1) << 16);
}

__global__ void prep_kernel(const float* __restrict__ Wa, const float* __restrict__ Wb,
                            const float* __restrict__ Wc, const float* __restrict__ Wd,
                            int* __restrict__ cnt, int* __restrict__ flag) {
    int task = blockIdx.x * blockDim.x + threadIdx.x;   // 0..8191
    for (int i = task; i < NTOT; i += 8192) cnt[i] = 0;
    if (task < 2) flag[task] = 0;
    int m = task >> 11;
    int tt = task & 2047;
    int n = tt & 127, kg = tt >> 7;
    const float* W = (m == 0) ? Wa : (m == 1) ? Wb : (m == 2) ? Wc : Wd;
    float v[8];
    #pragma unroll
    for (int j = 0; j < 8; j++) v[j] = __ldg(W + (kg * 8 + j) * D + n);
    uint32_t hi[4], lo[4];
    split8(v, hi, lo);
    int half = kg >> 3, kgl = kg & 7;
    int idx = n * 9 + kgl;
    g_wt[m][half][0][idx] = make_uint4(hi[0], hi[1], hi[2], hi[3]);
    g_wt[m][half][1][idx] = make_uint4(lo[0], lo[1], lo[2], lo[3]);
}

// ---------------- CSR build (single graph per launch) ----------------
__global__ void hist_kernel(const int* __restrict__ dst, int* __restrict__ cnt, int E) {
    int e = blockIdx.x * blockDim.x + threadIdx.x;
    if (e < E) atomicAdd(cnt + __ldg(dst + e), 1);
}

// block-local exclusive scan + block totals; LAST block also scans the totals.
__global__ void scan_blk_kernel(const int* __restrict__ cnt, int* __restrict__ ptr,
                                int* __restrict__ bsum, int* __restrict__ flag, int n) {
    __shared__ int wsum[32];
    __shared__ int tmp[128];
    __shared__ int is_last;
    int tid = threadIdx.x, lane = tid & 31, wid = tid >> 5;
    int i = blockIdx.x * 1024 + tid;
    int x = (i < n) ? cnt[i] : 0;
    int v = x;
    #pragma unroll
    for (int o = 1; o < 32; o <<= 1) { int t = __shfl_up_sync(~0u, v, o); if (lane >= o) v += t; }
    if (lane == 31) wsum[wid] = v;
    __syncthreads();
    if (wid == 0) {
        int s = wsum[lane];
        #pragma unroll
        for (int o = 1; o < 32; o <<= 1) { int t = __shfl_up_sync(~0u, s, o); if (lane >= o) s += t; }
        wsum[lane] = s;
    }
    __syncthreads();
    int woff = wid ? wsum[wid - 1] : 0;
    if (i < n) ptr[i] = woff + v - x;

    if (tid == 0) {
        bsum[blockIdx.x] = wsum[31];
        __threadfence();
        int old = atomicAdd(flag, 1);
        is_last = (old == (int)gridDim.x - 1) ? 1 : 0;
    }
    __syncthreads();
    if (is_last) {
        __threadfence();
        int nb = gridDim.x;                 // <= 64
        int xx = (tid < nb) ? bsum[tid] : 0;
        if (tid < 128) tmp[tid] = xx;
        __syncthreads();
        for (int o = 1; o < 128; o <<= 1) {
            int t = (tid >= o && tid < 128) ? tmp[tid - o] : 0;
            __syncthreads();
            if (tid < 128) tmp[tid] += t;
            __syncthreads();
        }
        if (tid < nb) bsum[tid] = tmp[tid] - xx;
    }
}

// finalize: ptr[i] = raw + bsum + base; cur[i] = same; ptr[n] = base + total
__global__ void scan_add_kernel(int* __restrict__ ptr, int* __restrict__ cur,
                                const int* __restrict__ bsum, int n, int base, int total) {
    int i = blockIdx.x * blockDim.x + threadIdx.x;
    if (i < n) {
        int v = ptr[i] + bsum[i >> 10] + base;
        ptr[i] = v;
        cur[i] = v;
    }
    if (i == 0) ptr[n] = base + total;
}

__global__ void scatter_kernel(const int* __restrict__ src, const int* __restrict__ dst,
                               const float* __restrict__ w,
                               int* __restrict__ cur, int2* __restrict__ edges, int E) {
    int e = blockIdx.x * blockDim.x + threadIdx.x;
    if (e >= E) return;
    int pos = atomicAdd(cur + __ldg(dst + e), 1);
    edges[pos] = make_int2(__ldg(src + e), __float_as_int(__ldg(w + e)));
}

// ---------------- CSR aggregation: one warp per dst node (R13 version) ----------------
__global__ void csr_agg_kernel(const float4* __restrict__ feat,
                               const int* __restrict__ ptr,
                               const int2* __restrict__ edges,
                               float* __restrict__ agg, int n) {
    int t = blockIdx.x * blockDim.x + threadIdx.x;
    int node = t >> 5;
    if (node >= n) return;
    int lane = t & 31;
    int beg = __ldg(ptr + node);
    int end = __ldg(ptr + node + 1);
    float4 a0 = make_float4(0.f, 0.f, 0.f, 0.f);
    float4 a1 = make_float4(0.f, 0.f, 0.f, 0.f);
    int i = beg;
    for (; i + 2 <= end; i += 2) {
        int2 e0 = __ldg(edges + i);
        int2 e1 = __ldg(edges + i + 1);
        float w0 = __int_as_float(e0.y), w1 = __int_as_float(e1.y);
        float4 v0 = __ldg(feat + (size_t)e0.x * 32 + lane);
        float4 v1 = __ldg(feat + (size_t)e1.x * 32 + lane);
        a0.x = fmaf(v0.x, w0, a0.x); a0.y = fmaf(v0.y, w0, a0.y);
        a0.z = fmaf(v0.z, w0, a0.z); a0.w = fmaf(v0.w, w0, a0.w);
        a1.x = fmaf(v1.x, w1, a1.x); a1.y = fmaf(v1.y, w1, a1.y);
        a1.z = fmaf(v1.z, w1, a1.z); a1.w = fmaf(v1.w, w1, a1.w);
    }
    if (i < end) {
        int2 e0 = __ldg(edges + i);
        float w0 = __int_as_float(e0.y);
        float4 v0 = __ldg(feat + (size_t)e0.x * 32 + lane);
        a0.x = fmaf(v0.x, w0, a0.x); a0.y = fmaf(v0.y, w0, a0.y);
        a0.z = fmaf(v0.z, w0, a0.z); a0.w = fmaf(v0.w, w0, a0.w);
    }
    ((float4*)agg)[(size_t)node * 32 + lane] =
        make_float4(a0.x + a1.x, a0.y + a1.y, a0.z + a1.z, a0.w + a1.w);
}

// ---------------- HMMA (mma.sync) MLP, pipelined W halves (R13 version) ----------------
#define SM_XHI  0
#define SM_XLO  (SM_XHI + XTILE_B)
#define SM_WS0  (SM_XLO + XTILE_B)
#define SM_WS1  (SM_WS0 + WHALF_B)
#define SM_WS2  (SM_WS1 + WHALF_B)
#define SM_WS3  (SM_WS2 + WHALF_B)
#define SM_B1   (SM_WS3 + WHALF_B)
#define SM_B2   (SM_B1 + 512)
#define SM_TOTAL (SM_B2 + 512)            // 109568 -> 2 CTAs/SM
#define SM_FST  SM_WS0
#define LDF     132

static __device__ __forceinline__ uint32_t smem_u32(const void* p) {
    uint32_t a;
    asm("{ .reg .u64 t; cvta.to.shared.u64 t, %1; cvt.u32.u64 %0, t; }" : "=r"(a) : "l"(p));
    return a;
}

static __device__ __forceinline__ void ldsm4(uint32_t* r, uint32_t addr) {
    asm volatile("ldmatrix.sync.aligned.m8n8.x4.shared.b16 {%0,%1,%2,%3}, [%4];"
                 : "=r"(r[0]), "=r"(r[1]), "=r"(r[2]), "=r"(r[3]) : "r"(addr));
}

static __device__ __forceinline__ void mma16816(float* d, const uint32_t* a,
                                                uint32_t b0, uint32_t b1) {
    asm volatile("mma.sync.aligned.m16n8k16.row.col.f32.bf16.bf16.f32 "
                 "{%0,%1,%2,%3}, {%4,%5,%6,%7}, {%8,%9}, {%0,%1,%2,%3};"
                 : "+f"(d[0]), "+f"(d[1]), "+f"(d[2]), "+f"(d[3])
                 : "r"(a[0]), "r"(a[1]), "r"(a[2]), "r"(a[3]), "r"(b0), "r"(b1));
}

static __device__ __forceinline__ void stage_whalf(uint32_t smb, uint32_t hi_off, uint32_t lo_off,
                                                   const uint4* __restrict__ half_base, int tid) {
    const uint4* hi = half_base;
    const uint4* lo = half_base + WHALF_U4;
    for (int i = tid; i < WHALF_U4; i += 256) {
        asm volatile("cp.async.cg.shared.global [%0], [%1], 16;"
                     :: "r"(smb + hi_off + (uint32_t)i * 16), "l"(hi + i));
        asm volatile("cp.async.cg.shared.global [%0], [%1], 16;"
                     :: "r"(smb + lo_off + (uint32_t)i * 16), "l"(lo + i));
    }
    asm volatile("cp.async.commit_group;" ::: "memory");
}
template <int N>
static __device__ __forceinline__ void wait_cp_n() {
    asm volatile("cp.async.wait_group %0;" :: "n"(N) : "memory");
}

// one k-half of a layer, 2x4 warp grid
static __device__ __forceinline__ void do_half(uint32_t smb, uint32_t whi, uint32_t wlo,
                                               int khalf, int mg, int ng, int lane,
                                               float acc[8][4]) {
    const int rsel = lane & 15;
    const uint32_t koff = (uint32_t)((lane >> 4) << 4);
    #pragma unroll
    for (int kk = 0; kk < 4; kk++) {
        uint32_t rowkA = (uint32_t)(khalf * 4 + kk) * 32 + koff;
        uint32_t rowkB = (uint32_t)kk * 32 + koff;
        uint32_t bh[2][4], bl[2][4];
        #pragma unroll
        for (int nb = 0; nb < 2; nb++) {
            uint32_t boff = (uint32_t)(ng * 32 + nb * 16 + rsel) * LDW_B + rowkB;
            ldsm4(bh[nb], smb + whi + boff);
            ldsm4(bl[nb], smb + wlo + boff);
        }
        #pragma unroll
        for (int mt = 0; mt < 2; mt++) {
            uint32_t aoff = (uint32_t)(mg * 32 + mt * 16 + rsel) * LDB_B + rowkA;
            uint32_t ahi[4], alo[4];
            ldsm4(ahi, smb + SM_XHI + aoff);
            ldsm4(alo, smb + SM_XLO + aoff);
            #pragma unroll
            for (int nb = 0; nb < 2; nb++) {
                float* d0 = acc[mt * 4 + nb * 2];
                float* d1 = acc[mt * 4 + nb * 2 + 1];
                mma16816(d0, ahi, bh[nb][0], bh[nb][2]);
                mma16816(d1, ahi, bh[nb][1], bh[nb][3]);
                mma16816(d0, ahi, bl[nb][0], bl[nb][2]);
                mma16816(d1, ahi, bl[nb][1], bl[nb][3]);
                mma16816(d0, alo, bh[nb][0], bh[nb][2]);
                mma16816(d1, alo, bh[nb][1], bh[nb][3]);
            }
        }
    }
}

__global__ void __launch_bounds__(256, 2)
mlp_tc_kernel(const float* __restrict__ feat, const float* __restrict__ agg,
              const uint4* __restrict__ wmat1, const uint4* __restrict__ wmat2,
              const float* __restrict__ b1, const float* __restrict__ b2,
              const float* __restrict__ eps_p,
              float* __restrict__ h_out, float* __restrict__ out, int N) {
    extern __shared__ char sm[];
    const uint32_t smb = smem_u32(sm);
    const int tid = threadIdx.x;
    const int wid = tid >> 5;
    const int lane = tid & 31;
    const int mg = wid & 1;            // 2 m-groups of 32 rows
    const int ng = wid >> 1;           // 4 n-groups of 32 cols
    const int row0 = blockIdx.x * BM;
    const float eps1 = 1.f + __ldg(eps_p);

    const float4* feat4 = (const float4*)feat;
    const float4* agg4  = (const float4*)agg;
    float* sB1 = (float*)(sm + SM_B1);
    float* sB2 = (float*)(sm + SM_B2);

    // prefetch W1 (both halves) under X staging
    stage_whalf(smb, SM_WS0, SM_WS1, wmat1, tid);                 // group: W1h1
    stage_whalf(smb, SM_WS2, SM_WS3, wmat1 + 2 * WHALF_U4, tid);  // group: W1h2

    if (tid < 128) {
        sB1[tid] = __ldg(b1 + tid);
        sB2[tid] = __ldg(b2 + tid);
    }

    // ---- stage x = (1+eps)*feat + agg as bf16 hi/lo (64 rows) ----
    #pragma unroll
    for (int i = 0; i < 4; i++) {
        int tt = tid + i * 256;
        int tr = tt >> 4, kg = tt & 15;
        int grow = row0 + tr;
        float v[8];
        if (grow < N) {
            float4 f0 = __ldg(feat4 + (size_t)grow * 32 + kg * 2);
            float4 f1 = __ldg(feat4 + (size_t)grow * 32 + kg * 2 + 1);
            float4 a0 = __ldg(agg4  + (size_t)grow * 32 + kg * 2);
            float4 a1 = __ldg(agg4  + (size_t)grow * 32 + kg * 2 + 1);
            v[0] = fmaf(eps1, f0.x, a0.x); v[1] = fmaf(eps1, f0.y, a0.y);
            v[2] = fmaf(eps1, f0.z, a0.z); v[3] = fmaf(eps1, f0.w, a0.w);
            v[4] = fmaf(eps1, f1.x, a1.x); v[5] = fmaf(eps1, f1.y, a1.y);
            v[6] = fmaf(eps1, f1.z, a1.z); v[7] = fmaf(eps1, f1.w, a1.w);
        } else {
            #pragma unroll
            for (int j = 0; j < 8; j++) v[j] = 0.f;
        }
        uint32_t hi[4], lo[4];
        split8(v, hi, lo);
        uint32_t off = (uint32_t)tr * LDB_B + (uint32_t)kg * 16;
        *(uint4*)(sm + SM_XHI + off) = make_uint4(hi[0], hi[1], hi[2], hi[3]);
        *(uint4*)(sm + SM_XLO + off) = make_uint4(lo[0], lo[1], lo[2], lo[3]);
    }

    float acc[8][4];
    #pragma unroll
    for (int t = 0; t < 8; t++)
        #pragma unroll
        for (int j = 0; j < 4; j++) acc[t][j] = 0.f;

    wait_cp_n<1>();          // W1h1 arrived
    __syncthreads();

    // ---- L1 half a (k 0..63) ----
    do_half(smb, SM_WS0, SM_WS1, 0, mg, ng, lane, acc);

    wait_cp_n<0>();          // W1h2 arrived
    __syncthreads();         // all warps done reading WS0/1
    stage_whalf(smb, SM_WS0, SM_WS1, wmat2, tid);   // W2h1 streams under L1b

    // ---- L1 half b (k 64..127) ----
    do_half(smb, SM_WS2, SM_WS3, 1, mg, ng, lane, acc);
    __syncthreads();         // all warps done reading X (and W1h2)

    // writeback h1 = leaky(acc + b1) into X tiles
    {
        const int c0 = 2 * (lane & 3);
        #pragma unroll
        for (int mt = 0; mt < 2; mt++) {
            const int r0 = mg * 32 + mt * 16 + (lane >> 2);
            #pragma unroll
            for (int nb = 0; nb < 2; nb++) {
                #pragma unroll
                for (int s = 0; s < 2; s++) {
                    int c = ng * 32 + nb * 16 + s * 8 + c0;
                    const float* a = acc[mt * 4 + nb * 2 + s];
                    float v0 = leaky(a[0] + sB1[c]);
                    float v1 = leaky(a[1] + sB1[c + 1]);
                    float v2 = leaky(a[2] + sB1[c]);
                    float v3 = leaky(a[3] + sB1[c + 1]);
                    uint32_t h01, l01, h23, l23;
                    split2(v0, v1, h01, l01);
                    split2(v2, v3, h23, l23);
                    uint32_t o0 = (uint32_t)r0 * LDB_B + (uint32_t)c * 2;
                    uint32_t o1 = o0 + 8u * LDB_B;
                    *(uint32_t*)(sm + SM_XHI + o0) = h01;
                    *(uint32_t*)(sm + SM_XLO + o0) = l01;
                    *(uint32_t*)(sm + SM_XHI + o1) = h23;
                    *(uint32_t*)(sm + SM_XLO + o1) = l23;
                }
            }
        }
    }

    #pragma unroll
    for (int t = 0; t < 8; t++)
        #pragma unroll
        for (int j = 0; j < 4; j++) acc[t][j] = 0.f;

    wait_cp_n<0>();          // W2h1 arrived
    __syncthreads();         // h1 writeback visible; W2h1 visible
    stage_whalf(smb, SM_WS2, SM_WS3, wmat2 + 2 * WHALF_U4, tid);  // W2h2 under L2a

    // ---- L2 half a ----
    do_half(smb, SM_WS0, SM_WS1, 0, mg, ng, lane, acc);

    wait_cp_n<0>();          // W2h2 arrived
    __syncthreads();
    // ---- L2 half b ----
    do_half(smb, SM_WS2, SM_WS3, 1, mg, ng, lane, acc);

    // epilogue staging (reuses WS0/1; all warps past L2a reads)
    __syncthreads();
    {
        float* fst = (float*)(sm + SM_FST);
        const int c0 = 2 * (lane & 3);
        #pragma unroll
        for (int mt = 0; mt < 2; mt++) {
            const int r0 = mg * 32 + mt * 16 + (lane >> 2);
            #pragma unroll
            for (int nb = 0; nb < 2; nb++) {
                #pragma unroll
                for (int s = 0; s < 2; s++) {
                    int c = ng * 32 + nb * 16 + s * 8 + c0;
                    const float* a = acc[mt * 4 + nb * 2 + s];
                    float v0 = leaky(a[0] + sB2[c]);
                    float v1 = leaky(a[1] + sB2[c + 1]);
                    float v2 = leaky(a[2] + sB2[c]);
                    float v3 = leaky(a[3] + sB2[c + 1]);
                    *(float2*)(fst + (size_t)r0 * LDF + c)       = make_float2(v0, v1);
                    *(float2*)(fst + (size_t)(r0 + 8) * LDF + c) = make_float2(v2, v3);
                }
            }
        }
    }
    __syncthreads();

    // coalesced final writes: out = h2 + feat; h_out = h2
    {
        const float* fst = (const float*)(sm + SM_FST);
        #pragma unroll
        for (int i = 0; i < 8; i++) {
            int idx = tid + i * 256;
            int r = idx >> 5, c4 = idx & 31;
            int grow = row0 + r;
            if (grow >= N) continue;
            const float* p = fst + (size_t)r * LDF + c4 * 4;
            float4 h = make_float4(p[0], p[1], p[2], p[3]);
            float4 fv = __ldg(feat4 + (size_t)grow * 32 + c4);
            ((float4*)out)[(size_t)grow * 32 + c4] =
                make_float4(h.x + fv.x, h.y + fv.y, h.z + fv.z, h.w + fv.w);
            if (h_out)
                ((float4*)h_out)[(size_t)grow * 32 + c4] = h;
        }
    }
}

extern "C" void kernel_launch(void* const* d_in, const int* in_sizes, int n_in,
                              void* d_out, int out_size) {
    const float* feat_row = (const float*)d_in[0];
    const float* feat_col = (const float*)d_in[1];
    const int*   src_c2r  = (const int*)d_in[2];
    const int*   dst_c2r  = (const int*)d_in[3];
    const float* w_c2r    = (const float*)d_in[4];
    const int*   src_r2c  = (const int*)d_in[5];
    const int*   dst_r2c  = (const int*)d_in[6];
    const float* w_r2c    = (const float*)d_in[7];
    const float* W1_c2r   = (const float*)d_in[8];
    const float* b1_c2r   = (const float*)d_in[9];
    const float* W2_c2r   = (const float*)d_in[10];
    const float* b2_c2r   = (const float*)d_in[11];
    const float* W1_r2c   = (const float*)d_in[12];
    const float* b1_r2c   = (const float*)d_in[13];
    const float* W2_r2c   = (const float*)d_in[14];
    const float* b2_r2c   = (const float*)d_in[15];
    const float* eps_c2r  = (const float*)d_in[16];
    const float* eps_r2c  = (const float*)d_in[17];

    const int E = in_sizes[2];

    float* out_row = (float*)d_out;
    float* out_col = out_row + (size_t)NROW * D;

    float *agg1, *agg2, *hrow;
    uint4* wt;
    int *cnt, *ptr, *cur, *bsum, *flag;
    int2* edges;
    cudaGetSymbolAddress((void**)&agg1,  g_agg1);
    cudaGetSymbolAddress((void**)&agg2,  g_agg2);
    cudaGetSymbolAddress((void**)&hrow,  g_hrow);
    cudaGetSymbolAddress((void**)&wt,    g_wt);
    cudaGetSymbolAddress((void**)&cnt,   g_cnt);
    cudaGetSymbolAddress((void**)&ptr,   g_ptr);
    cudaGetSymbolAddress((void**)&cur,   g_cur);
    cudaGetSymbolAddress((void**)&bsum,  g_bsum);
    cudaGetSymbolAddress((void**)&flag,  g_flag);
    cudaGetSymbolAddress((void**)&edges, g_edges);

    int* ptr1 = ptr;                 // [NROW+1]
    int* ptr2 = ptr + NROW + 1;      // [NCOL+1]
    int* bsum1 = bsum;
    int* bsum2 = bsum + 64;

    const int MAT_U4 = 2 * 2 * WHALF_U4;
    const uint4* w1_a = wt + 0 * MAT_U4;
    const uint4* w2_a = wt + 1 * MAT_U4;
    const uint4* w1_b = wt + 2 * MAT_U4;
    const uint4* w2_b = wt + 3 * MAT_U4;

    cudaFuncSetAttribute(mlp_tc_kernel, cudaFuncAttributeMaxDynamicSharedMemorySize, SM_TOTAL);

    // side stream + fork/join events (created once, on the uncaptured first call)
    static cudaStream_t s2 = nullptr;
    static cudaEvent_t evFork = nullptr, evJoin = nullptr;
    if (!s2) {
        cudaStreamCreateWithFlags(&s2, cudaStreamNonBlocking);
        cudaEventCreateWithFlags(&evFork, cudaEventDisableTiming);
        cudaEventCreateWithFlags(&evJoin, cudaEventDisableTiming);
    }

    const int egrid = (E + 255) / 256;
    const int g_row = (NROW + BM - 1) / BM;
    const int g_col = (NCOL + BM - 1) / BM;
    const int nsb1 = (NROW + 1023) / 1024;     // 49
    const int nsb2 = (NCOL + 1023) / 1024;     // 49
    const int agg_grid1 = (NROW * 32 + 255) / 256;
    const int agg_grid2 = (NCOL * 32 + 255) / 256;

    // ---- shared prep (weights + counters) ----
    prep_kernel<<<32, 256>>>(W1_c2r, W2_c2r, W1_r2c, W2_r2c, cnt, flag);
    cudaEventRecord(evFork, 0);
    cudaStreamWaitEvent(s2, evFork, 0);

    // ---- stream B: graph2 CSR build (hidden under graph1 build + pass 1) ----
    hist_kernel<<<egrid, 256, 0, s2>>>(dst_r2c, cnt + NROW, E);
    scan_blk_kernel<<<nsb2, 1024, 0, s2>>>(cnt + NROW, ptr2, bsum2, flag + 1, NCOL);
    scan_add_kernel<<<(NCOL + 255) / 256, 256, 0, s2>>>(ptr2, cur + NROW, bsum2, NCOL, E, E);
    scatter_kernel<<<egrid, 256, 0, s2>>>(src_r2c, dst_r2c, w_r2c, cur + NROW, edges, E);
    cudaEventRecord(evJoin, s2);

    // ---- stream A (default): graph1 CSR build + pass 1 ----
    hist_kernel<<<egrid, 256>>>(dst_c2r, cnt, E);
    scan_blk_kernel<<<nsb1, 1024>>>(cnt, ptr1, bsum1, flag, NROW);
    scan_add_kernel<<<(NROW + 255) / 256, 256>>>(ptr1, cur, bsum1, NROW, 0, E);
    scatter_kernel<<<egrid, 256>>>(src_c2r, dst_c2r, w_c2r, cur, edges, E);
    csr_agg_kernel<<<agg_grid1, 256>>>((const float4*)feat_col, ptr1, edges, agg1, NROW);
    mlp_tc_kernel<<<g_row, 256, SM_TOTAL>>>(feat_row, agg1, w1_a, w2_a,
                                            b1_c2r, b2_c2r, eps_c2r, hrow, out_row, NROW);

    // ---- join, then pass 2 (gathers from updated h_row via graph2 CSR) ----
    cudaStreamWaitEvent((cudaStream_t)0, evJoin, 0);
    csr_agg_kernel<<<agg_grid2, 256>>>((const float4*)hrow, ptr2, edges, agg2, NCOL);
    mlp_tc_kernel<<<g_col, 256, SM_TOTAL>>>(feat_col, agg2, w1_b, w2_b,
                                            b1_r2c, b2_r2c, eps_r2c, nullptr, out_col, NCOL);
}

// round 17
// speedup vs baseline: 1.0704x; 1.0263x over previous
#include <cuda_runtime.h>
#include <cuda_bf16.h>
#include <cstdint>

#define D      128
#define NROW   50000
#define NCOL   50000
#define NTOT   (NROW + NCOL)
#define BM     64

// X tile: 64 rows x 128 k bf16, row stride 272B
#define LDB_B   272
#define XTILE_B (64 * LDB_B)          // 17408
// W half-tile: 128 n-rows x 64 k bf16, row stride 144B
#define LDW_B   144
#define WHALF_B (128 * LDW_B)         // 18432
#define WHALF_U4 (WHALF_B / 16)       // 1152

// Scratch (alloc-free rule: __device__ globals)
__device__ float g_agg1[(size_t)NROW * D];
__device__ float g_agg2[(size_t)NCOL * D];
__device__ float g_hrow[(size_t)NROW * D];
__device__ uint4 g_wt[4][2][2][WHALF_U4];   // [matrix][khalf][hi/lo]
__device__ int   g_cnt[NTOT];
__device__ int   g_ptr[NTOT + 2];           // ptr1[NROW+1] then ptr2[NCOL+1]
__device__ int   g_cur[NTOT];
__device__ int   g_bsum[128];               // [0:64) graph1, [64:128) graph2
__device__ int   g_flag[4];                 // A1, D1, A2, D2
__device__ int2  g_edges[1200000];

__device__ __forceinline__ float leaky(float v) { return v >= 0.f ? v : 0.01f * v; }

static __device__ __forceinline__ void split8(const float* x, uint32_t* hi, uint32_t* lo) {
    #pragma unroll
    for (int j = 0; j < 4; j++) {
        __nv_bfloat16 h0 = __float2bfloat16(x[2*j]);
        __nv_bfloat16 h1 = __float2bfloat16(x[2*j+1]);
        __nv_bfloat16 l0 = __float2bfloat16(x[2*j]   - __bfloat162float(h0));
        __nv_bfloat16 l1 = __float2bfloat16(x[2*j+1] - __bfloat162float(h1));
        hi[j] = (uint32_t)__bfloat16_as_ushort(h0) | ((uint32_t)__bfloat16_as_ushort(h1) << 16);
        lo[j] = (uint32_t)__bfloat16_as_ushort(l0) | ((uint32_t)__bfloat16_as_ushort(l1) << 16);
    }
}

static __device__ __forceinline__ void split2(float x0, float x1, uint32_t& hi, uint32_t& lo) {
    __nv_bfloat16 h0 = __float2bfloat16(x0);
    __nv_bfloat16 h1 = __float2bfloat16(x1);
    __nv_bfloat16 l0 = __float2bfloat16(x0 - __bfloat162float(h0));
    __nv_bfloat16 l1 = __float2bfloat16(x1 - __bfloat162float(h1));
    hi = (uint32_t)__bfloat16_as_ushort(h0) | ((uint32_t)__bfloat16_as_ushort(h1) << 16);
    lo = (uint32_t)__bfloat16_as_ushort(l0) | ((uint32_t)__bfloat16_as_ushort(l1) << 16);
}

// ---------------- minimal zero (critical path head) ----------------
__global__ void zero_kernel(int* __restrict__ cnt, int* __restrict__ flag) {
    int i = blockIdx.x * blockDim.x + threadIdx.x;
    if (i < NTOT) cnt[i] = 0;
    if (i < 4) flag[i] = 0;
}

// ---------------- weight pre-split (runs on side stream) ----------------
__global__ void split_w_kernel(const float* __restrict__ Wa, const float* __restrict__ Wb,
                               const float* __restrict__ Wc, const float* __restrict__ Wd) {
    int task = blockIdx.x * blockDim.x + threadIdx.x;   // 0..8191
    int m = task >> 11;
    int tt = task & 2047;
    int n = tt & 127, kg = tt >> 7;
    const float* W = (m == 0) ? Wa : (m == 1) ? Wb : (m == 2) ? Wc : Wd;
    float v[8];
    #pragma unroll
    for (int j = 0; j < 8; j++) v[j] = __ldg(W + (kg * 8 + j) * D + n);
    uint32_t hi[4], lo[4];
    split8(v, hi, lo);
    int half = kg >> 3, kgl = kg & 7;
    int idx = n * 9 + kgl;
    g_wt[m][half][0][idx] = make_uint4(hi[0], hi[1], hi[2], hi[3]);
    g_wt[m][half][1][idx] = make_uint4(lo[0], lo[1], lo[2], lo[3]);
}

// ---------------- CSR build (single graph per launch) ----------------
__global__ void hist_kernel(const int* __restrict__ dst, int* __restrict__ cnt, int E) {
    int e = blockIdx.x * blockDim.x + threadIdx.x;
    if (e < E) atomicAdd(cnt + __ldg(dst + e), 1);
}

// fused block scan + cross-block offset (grid-resident two-phase; nb <= 64 blocks
// of 1024 threads, all co-resident on 148 SMs so spinning is deadlock-free).
__global__ void scan_full_kernel(const int* __restrict__ cnt, int* __restrict__ ptr,
                                 int* __restrict__ cur, int* __restrict__ bsum,
                                 int* __restrict__ flagA, int* __restrict__ flagD,
                                 int n, int base, int total) {
    __shared__ int wsum[32];
    __shared__ int tmp[128];
    __shared__ int is_last;
    __shared__ int soff;
    int tid = threadIdx.x, lane = tid & 31, wid = tid >> 5;
    int i = blockIdx.x * 1024 + tid;
    int x = (i < n) ? cnt[i] : 0;
    int v = x;
    #pragma unroll
    for (int o = 1; o < 32; o <<= 1) { int t = __shfl_up_sync(~0u, v, o); if (lane >= o) v += t; }
    if (lane == 31) wsum[wid] = v;
    __syncthreads();
    if (wid == 0) {
        int s = wsum[lane];
        #pragma unroll
        for (int o = 1; o < 32; o <<= 1) { int t = __shfl_up_sync(~0u, s, o); if (lane >= o) s += t; }
        wsum[lane] = s;
    }
    __syncthreads();
    int woff = wid ? wsum[wid - 1] : 0;
    int loc = woff + v - x;                  // block-local exclusive prefix

    if (tid == 0) {
        atomicExch(bsum + blockIdx.x, wsum[31]);   // block total (L2-coherent)
        int old = atomicAdd(flagA, 1);
        is_last = (old == (int)gridDim.x - 1) ? 1 : 0;
    }
    __syncthreads();

    if (is_last) {
        int nb = gridDim.x;
        int xx = (tid < nb) ? atomicAdd(bsum + tid, 0) : 0;
        if (tid < 128) tmp[tid] = xx;
        __syncthreads();
        for (int o = 1; o < 128; o <<= 1) {
            int t = (tid >= o && tid < 128) ? tmp[tid - o] : 0;
            __syncthreads();
            if (tid < 128) tmp[tid] += t;
            __syncthreads();
        }
        if (tid < nb) atomicExch(bsum + tid, tmp[tid] - xx);   // exclusive offsets
        if (tid == 0) {
            ptr[n] = base + total;
            __threadfence();
            atomicExch(flagD, 1);
        }
    }
    if (tid == 0) {
        while (atomicAdd(flagD, 0) == 0) {}
        soff = atomicAdd(bsum + blockIdx.x, 0);
    }
    __syncthreads();
    if (i < n) {
        int pv = loc + soff + base;
        ptr[i] = pv;
        cur[i] = pv;
    }
}

__global__ void scatter_kernel(const int* __restrict__ src, const int* __restrict__ dst,
                               const float* __restrict__ w,
                               int* __restrict__ cur, int2* __restrict__ edges, int E) {
    int e = blockIdx.x * blockDim.x + threadIdx.x;
    if (e >= E) return;
    int pos = atomicAdd(cur + __ldg(dst + e), 1);
    edges[pos] = make_int2(__ldg(src + e), __float_as_int(__ldg(w + e)));
}

// ---------------- CSR aggregation: one warp per dst node (R13/R16 version) ----------------
__global__ void csr_agg_kernel(const float4* __restrict__ feat,
                               const int* __restrict__ ptr,
                               const int2* __restrict__ edges,
                               float* __restrict__ agg, int n) {
    int t = blockIdx.x * blockDim.x + threadIdx.x;
    int node = t >> 5;
    if (node >= n) return;
    int lane = t & 31;
    int beg = __ldg(ptr + node);
    int end = __ldg(ptr + node + 1);
    float4 a0 = make_float4(0.f, 0.f, 0.f, 0.f);
    float4 a1 = make_float4(0.f, 0.f, 0.f, 0.f);
    int i = beg;
    for (; i + 2 <= end; i += 2) {
        int2 e0 = __ldg(edges + i);
        int2 e1 = __ldg(edges + i + 1);
        float w0 = __int_as_float(e0.y), w1 = __int_as_float(e1.y);
        float4 v0 = __ldg(feat + (size_t)e0.x * 32 + lane);
        float4 v1 = __ldg(feat + (size_t)e1.x * 32 + lane);
        a0.x = fmaf(v0.x, w0, a0.x); a0.y = fmaf(v0.y, w0, a0.y);
        a0.z = fmaf(v0.z, w0, a0.z); a0.w = fmaf(v0.w, w0, a0.w);
        a1.x = fmaf(v1.x, w1, a1.x); a1.y = fmaf(v1.y, w1, a1.y);
        a1.z = fmaf(v1.z, w1, a1.z); a1.w = fmaf(v1.w, w1, a1.w);
    }
    if (i < end) {
        int2 e0 = __ldg(edges + i);
        float w0 = __int_as_float(e0.y);
        float4 v0 = __ldg(feat + (size_t)e0.x * 32 + lane);
        a0.x = fmaf(v0.x, w0, a0.x); a0.y = fmaf(v0.y, w0, a0.y);
        a0.z = fmaf(v0.z, w0, a0.z); a0.w = fmaf(v0.w, w0, a0.w);
    }
    ((float4*)agg)[(size_t)node * 32 + lane] =
        make_float4(a0.x + a1.x, a0.y + a1.y, a0.z + a1.z, a0.w + a1.w);
}

// ---------------- HMMA (mma.sync) MLP, pipelined W halves (R13/R16 version) ----------------
#define SM_XHI  0
#define SM_XLO  (SM_XHI + XTILE_B)
#define SM_WS0  (SM_XLO + XTILE_B)
#define SM_WS1  (SM_WS0 + WHALF_B)
#define SM_WS2  (SM_WS1 + WHALF_B)
#define SM_WS3  (SM_WS2 + WHALF_B)
#define SM_B1   (SM_WS3 + WHALF_B)
#define SM_B2   (SM_B1 + 512)
#define SM_TOTAL (SM_B2 + 512)            // 109568 -> 2 CTAs/SM
#define SM_FST  SM_WS0
#define LDF     132

static __device__ __forceinline__ uint32_t smem_u32(const void* p) {
    uint32_t a;
    asm("{ .reg .u64 t; cvta.to.shared.u64 t, %1; cvt.u32.u64 %0, t; }" : "=r"(a) : "l"(p));
    return a;
}

static __device__ __forceinline__ void ldsm4(uint32_t* r, uint32_t addr) {
    asm volatile("ldmatrix.sync.aligned.m8n8.x4.shared.b16 {%0,%1,%2,%3}, [%4];"
                 : "=r"(r[0]), "=r"(r[1]), "=r"(r[2]), "=r"(r[3]) : "r"(addr));
}

static __device__ __forceinline__ void mma16816(float* d, const uint32_t* a,
                                                uint32_t b0, uint32_t b1) {
    asm volatile("mma.sync.aligned.m16n8k16.row.col.f32.bf16.bf16.f32 "
                 "{%0,%1,%2,%3}, {%4,%5,%6,%7}, {%8,%9}, {%0,%1,%2,%3};"
                 : "+f"(d[0]), "+f"(d[1]), "+f"(d[2]), "+f"(d[3])
                 : "r"(a[0]), "r"(a[1]), "r"(a[2]), "r"(a[3]), "r"(b0), "r"(b1));
}

static __device__ __forceinline__ void stage_whalf(uint32_t smb, uint32_t hi_off, uint32_t lo_off,
                                                   const uint4* __restrict__ half_base, int tid) {
    const uint4* hi = half_base;
    const uint4* lo = half_base + WHALF_U4;
    for (int i = tid; i < WHALF_U4; i += 256) {
        asm volatile("cp.async.cg.shared.global [%0], [%1], 16;"
                     :: "r"(smb + hi_off + (uint32_t)i * 16), "l"(hi + i));
        asm volatile("cp.async.cg.shared.global [%0], [%1], 16;"
                     :: "r"(smb + lo_off + (uint32_t)i * 16), "l"(lo + i));
    }
    asm volatile("cp.async.commit_group;" ::: "memory");
}
template <int N>
static __device__ __forceinline__ void wait_cp_n() {
    asm volatile("cp.async.wait_group %0;" :: "n"(N) : "memory");
}

// one k-half of a layer, 2x4 warp grid
static __device__ __forceinline__ void do_half(uint32_t smb, uint32_t whi, uint32_t wlo,
                                               int khalf, int mg, int ng, int lane,
                                               float acc[8][4]) {
    const int rsel = lane & 15;
    const uint32_t koff = (uint32_t)((lane >> 4) << 4);
    #pragma unroll
    for (int kk = 0; kk < 4; kk++) {
        uint32_t rowkA = (uint32_t)(khalf * 4 + kk) * 32 + koff;
        uint32_t rowkB = (uint32_t)kk * 32 + koff;
        uint32_t bh[2][4], bl[2][4];
        #pragma unroll
        for (int nb = 0; nb < 2; nb++) {
            uint32_t boff = (uint32_t)(ng * 32 + nb * 16 + rsel) * LDW_B + rowkB;
            ldsm4(bh[nb], smb + whi + boff);
            ldsm4(bl[nb], smb + wlo + boff);
        }
        #pragma unroll
        for (int mt = 0; mt < 2; mt++) {
            uint32_t aoff = (uint32_t)(mg * 32 + mt * 16 + rsel) * LDB_B + rowkA;
            uint32_t ahi[4], alo[4];
            ldsm4(ahi, smb + SM_XHI + aoff);
            ldsm4(alo, smb + SM_XLO + aoff);
            #pragma unroll
            for (int nb = 0; nb < 2; nb++) {
                float* d0 = acc[mt * 4 + nb * 2];
                float* d1 = acc[mt * 4 + nb * 2 + 1];
                mma16816(d0, ahi, bh[nb][0], bh[nb][2]);
                mma16816(d1, ahi, bh[nb][1], bh[nb][3]);
                mma16816(d0, ahi, bl[nb][0], bl[nb][2]);
                mma16816(d1, ahi, bl[nb][1], bl[nb][3]);
                mma16816(d0, alo, bh[nb][0], bh[nb][2]);
                mma16816(d1, alo, bh[nb][1], bh[nb][3]);
            }
        }
    }
}

__global__ void __launch_bounds__(256, 2)
mlp_tc_kernel(const float* __restrict__ feat, const float* __restrict__ agg,
              const uint4* __restrict__ wmat1, const uint4* __restrict__ wmat2,
              const float* __restrict__ b1, const float* __restrict__ b2,
              const float* __restrict__ eps_p,
              float* __restrict__ h_out, float* __restrict__ out, int N) {
    extern __shared__ char sm[];
    const uint32_t smb = smem_u32(sm);
    const int tid = threadIdx.x;
    const int wid = tid >> 5;
    const int lane = tid & 31;
    const int mg = wid & 1;            // 2 m-groups of 32 rows
    const int ng = wid >> 1;           // 4 n-groups of 32 cols
    const int row0 = blockIdx.x * BM;
    const float eps1 = 1.f + __ldg(eps_p);

    const float4* feat4 = (const float4*)feat;
    const float4* agg4  = (const float4*)agg;
    float* sB1 = (float*)(sm + SM_B1);
    float* sB2 = (float*)(sm + SM_B2);

    // prefetch W1 (both halves) under X staging
    stage_whalf(smb, SM_WS0, SM_WS1, wmat1, tid);                 // group: W1h1
    stage_whalf(smb, SM_WS2, SM_WS3, wmat1 + 2 * WHALF_U4, tid);  // group: W1h2

    if (tid < 128) {
        sB1[tid] = __ldg(b1 + tid);
        sB2[tid] = __ldg(b2 + tid);
    }

    // ---- stage x = (1+eps)*feat + agg as bf16 hi/lo (64 rows) ----
    #pragma unroll
    for (int i = 0; i < 4; i++) {
        int tt = tid + i * 256;
        int tr = tt >> 4, kg = tt & 15;
        int grow = row0 + tr;
        float v[8];
        if (grow < N) {
            float4 f0 = __ldg(feat4 + (size_t)grow * 32 + kg * 2);
            float4 f1 = __ldg(feat4 + (size_t)grow * 32 + kg * 2 + 1);
            float4 a0 = __ldg(agg4  + (size_t)grow * 32 + kg * 2);
            float4 a1 = __ldg(agg4  + (size_t)grow * 32 + kg * 2 + 1);
            v[0] = fmaf(eps1, f0.x, a0.x); v[1] = fmaf(eps1, f0.y, a0.y);
            v[2] = fmaf(eps1, f0.z, a0.z); v[3] = fmaf(eps1, f0.w, a0.w);
            v[4] = fmaf(eps1, f1.x, a1.x); v[5] = fmaf(eps1, f1.y, a1.y);
            v[6] = fmaf(eps1, f1.z, a1.z); v[7] = fmaf(eps1, f1.w, a1.w);
        } else {
            #pragma unroll
            for (int j = 0; j < 8; j++) v[j] = 0.f;
        }
        uint32_t hi[4], lo[4];
        split8(v, hi, lo);
        uint32_t off = (uint32_t)tr * LDB_B + (uint32_t)kg * 16;
        *(uint4*)(sm + SM_XHI + off) = make_uint4(hi[0], hi[1], hi[2], hi[3]);
        *(uint4*)(sm + SM_XLO + off) = make_uint4(lo[0], lo[1], lo[2], lo[3]);
    }

    float acc[8][4];
    #pragma unroll
    for (int t = 0; t < 8; t++)
        #pragma unroll
        for (int j = 0; j < 4; j++) acc[t][j] = 0.f;

    wait_cp_n<1>();          // W1h1 arrived
    __syncthreads();

    // ---- L1 half a (k 0..63) ----
    do_half(smb, SM_WS0, SM_WS1, 0, mg, ng, lane, acc);

    wait_cp_n<0>();          // W1h2 arrived
    __syncthreads();         // all warps done reading WS0/1
    stage_whalf(smb, SM_WS0, SM_WS1, wmat2, tid);   // W2h1 streams under L1b

    // ---- L1 half b (k 64..127) ----
    do_half(smb, SM_WS2, SM_WS3, 1, mg, ng, lane, acc);
    __syncthreads();         // all warps done reading X (and W1h2)

    // writeback h1 = leaky(acc + b1) into X tiles
    {
        const int c0 = 2 * (lane & 3);
        #pragma unroll
        for (int mt = 0; mt < 2; mt++) {
            const int r0 = mg * 32 + mt * 16 + (lane >> 2);
            #pragma unroll
            for (int nb = 0; nb < 2; nb++) {
                #pragma unroll
                for (int s = 0; s < 2; s++) {
                    int c = ng * 32 + nb * 16 + s * 8 + c0;
                    const float* a = acc[mt * 4 + nb * 2 + s];
                    float v0 = leaky(a[0] + sB1[c]);
                    float v1 = leaky(a[1] + sB1[c + 1]);
                    float v2 = leaky(a[2] + sB1[c]);
                    float v3 = leaky(a[3] + sB1[c + 1]);
                    uint32_t h01, l01, h23, l23;
                    split2(v0, v1, h01, l01);
                    split2(v2, v3, h23, l23);
                    uint32_t o0 = (uint32_t)r0 * LDB_B + (uint32_t)c * 2;
                    uint32_t o1 = o0 + 8u * LDB_B;
                    *(uint32_t*)(sm + SM_XHI + o0) = h01;
                    *(uint32_t*)(sm + SM_XLO + o0) = l01;
                    *(uint32_t*)(sm + SM_XHI + o1) = h23;
                    *(uint32_t*)(sm + SM_XLO + o1) = l23;
                }
            }
        }
    }

    #pragma unroll
    for (int t = 0; t < 8; t++)
        #pragma unroll
        for (int j = 0; j < 4; j++) acc[t][j] = 0.f;

    wait_cp_n<0>();          // W2h1 arrived
    __syncthreads();         // h1 writeback visible; W2h1 visible
    stage_whalf(smb, SM_WS2, SM_WS3, wmat2 + 2 * WHALF_U4, tid);  // W2h2 under L2a

    // ---- L2 half a ----
    do_half(smb, SM_WS0, SM_WS1, 0, mg, ng, lane, acc);

    wait_cp_n<0>();          // W2h2 arrived
    __syncthreads();
    // ---- L2 half b ----
    do_half(smb, SM_WS2, SM_WS3, 1, mg, ng, lane, acc);

    // epilogue staging (reuses WS0/1; all warps past L2a reads)
    __syncthreads();
    {
        float* fst = (float*)(sm + SM_FST);
        const int c0 = 2 * (lane & 3);
        #pragma unroll
        for (int mt = 0; mt < 2; mt++) {
            const int r0 = mg * 32 + mt * 16 + (lane >> 2);
            #pragma unroll
            for (int nb = 0; nb < 2; nb++) {
                #pragma unroll
                for (int s = 0; s < 2; s++) {
                    int c = ng * 32 + nb * 16 + s * 8 + c0;
                    const float* a = acc[mt * 4 + nb * 2 + s];
                    float v0 = leaky(a[0] + sB2[c]);
                    float v1 = leaky(a[1] + sB2[c + 1]);
                    float v2 = leaky(a[2] + sB2[c]);
                    float v3 = leaky(a[3] + sB2[c + 1]);
                    *(float2*)(fst + (size_t)r0 * LDF + c)       = make_float2(v0, v1);
                    *(float2*)(fst + (size_t)(r0 + 8) * LDF + c) = make_float2(v2, v3);
                }
            }
        }
    }
    __syncthreads();

    // coalesced final writes: out = h2 + feat; h_out = h2
    {
        const float* fst = (const float*)(sm + SM_FST);
        #pragma unroll
        for (int i = 0; i < 8; i++) {
            int idx = tid + i * 256;
            int r = idx >> 5, c4 = idx & 31;
            int grow = row0 + r;
            if (grow >= N) continue;
            const float* p = fst + (size_t)r * LDF + c4 * 4;
            float4 h = make_float4(p[0], p[1], p[2], p[3]);
            float4 fv = __ldg(feat4 + (size_t)grow * 32 + c4);
            ((float4*)out)[(size_t)grow * 32 + c4] =
                make_float4(h.x + fv.x, h.y + fv.y, h.z + fv.z, h.w + fv.w);
            if (h_out)
                ((float4*)h_out)[(size_t)grow * 32 + c4] = h;
        }
    }
}

extern "C" void kernel_launch(void* const* d_in, const int* in_sizes, int n_in,
                              void* d_out, int out_size) {
    const float* feat_row = (const float*)d_in[0];
    const float* feat_col = (const float*)d_in[1];
    const int*   src_c2r  = (const int*)d_in[2];
    const int*   dst_c2r  = (const int*)d_in[3];
    const float* w_c2r    = (const float*)d_in[4];
    const int*   src_r2c  = (const int*)d_in[5];
    const int*   dst_r2c  = (const int*)d_in[6];
    const float* w_r2c    = (const float*)d_in[7];
    const float* W1_c2r   = (const float*)d_in[8];
    const float* b1_c2r   = (const float*)d_in[9];
    const float* W2_c2r   = (const float*)d_in[10];
    const float* b2_c2r   = (const float*)d_in[11];
    const float* W1_r2c   = (const float*)d_in[12];
    const float* b1_r2c   = (const float*)d_in[13];
    const float* W2_r2c   = (const float*)d_in[14];
    const float* b2_r2c   = (const float*)d_in[15];
    const float* eps_c2r  = (const float*)d_in[16];
    const float* eps_r2c  = (const float*)d_in[17];

    const int E = in_sizes[2];

    float* out_row = (float*)d_out;
    float* out_col = out_row + (size_t)NROW * D;

    float *agg1, *agg2, *hrow;
    uint4* wt;
    int *cnt, *ptr, *cur, *bsum, *flag;
    int2* edges;
    cudaGetSymbolAddress((void**)&agg1,  g_agg1);
    cudaGetSymbolAddress((void**)&agg2,  g_agg2);
    cudaGetSymbolAddress((void**)&hrow,  g_hrow);
    cudaGetSymbolAddress((void**)&wt,    g_wt);
    cudaGetSymbolAddress((void**)&cnt,   g_cnt);
    cudaGetSymbolAddress((void**)&ptr,   g_ptr);
    cudaGetSymbolAddress((void**)&cur,   g_cur);
    cudaGetSymbolAddress((void**)&bsum,  g_bsum);
    cudaGetSymbolAddress((void**)&flag,  g_flag);
    cudaGetSymbolAddress((void**)&edges, g_edges);

    int* ptr1 = ptr;                 // [NROW+1]
    int* ptr2 = ptr + NROW + 1;      // [NCOL+1]
    int* bsum1 = bsum;
    int* bsum2 = bsum + 64;

    const int MAT_U4 = 2 * 2 * WHALF_U4;
    const uint4* w1_a = wt + 0 * MAT_U4;
    const uint4* w2_a = wt + 1 * MAT_U4;
    const uint4* w1_b = wt + 2 * MAT_U4;
    const uint4* w2_b = wt + 3 * MAT_U4;

    cudaFuncSetAttribute(mlp_tc_kernel, cudaFuncAttributeMaxDynamicSharedMemorySize, SM_TOTAL);

    // side stream + fork/join events (created once, on the uncaptured first call)
    static cudaStream_t s2 = nullptr;
    static cudaEvent_t evFork = nullptr, evW = nullptr, evJoin = nullptr;
    if (!s2) {
        cudaStreamCreateWithFlags(&s2, cudaStreamNonBlocking);
        cudaEventCreateWithFlags(&evFork, cudaEventDisableTiming);
        cudaEventCreateWithFlags(&evW, cudaEventDisableTiming);
        cudaEventCreateWithFlags(&evJoin, cudaEventDisableTiming);
    }

    const int egrid = (E + 255) / 256;
    const int g_row = (NROW + BM - 1) / BM;
    const int g_col = (NCOL + BM - 1) / BM;
    const int nsb1 = (NROW + 1023) / 1024;     // 49
    const int nsb2 = (NCOL + 1023) / 1024;     // 49
    const int agg_grid1 = (NROW * 32 + 255) / 256;
    const int agg_grid2 = (NCOL * 32 + 255) / 256;

    // ---- head: zero counters + flags (critical path), then fork ----
    zero_kernel<<<(NTOT + 255) / 256, 256>>>(cnt, flag);
    cudaEventRecord(evFork, 0);
    cudaStreamWaitEvent(s2, evFork, 0);

    // ---- stream B: weight split + graph2 CSR build (hidden under pass 1) ----
    split_w_kernel<<<32, 256, 0, s2>>>(W1_c2r, W2_c2r, W1_r2c, W2_r2c);
    cudaEventRecord(evW, s2);
    hist_kernel<<<egrid, 256, 0, s2>>>(dst_r2c, cnt + NROW, E);
    scan_full_kernel<<<nsb2, 1024, 0, s2>>>(cnt + NROW, ptr2, cur + NROW, bsum2,
                                            flag + 2, flag + 3, NCOL, E, E);
    scatter_kernel<<<egrid, 256, 0, s2>>>(src_r2c, dst_r2c, w_r2c, cur + NROW, edges, E);
    cudaEventRecord(evJoin, s2);

    // ---- stream A (default): graph1 CSR build + pass 1 ----
    hist_kernel<<<egrid, 256>>>(dst_c2r, cnt, E);
    scan_full_kernel<<<nsb1, 1024>>>(cnt, ptr1, cur, bsum1, flag, flag + 1, NROW, 0, E);
    scatter_kernel<<<egrid, 256>>>(src_c2r, dst_c2r, w_c2r, cur, edges, E);
    csr_agg_kernel<<<agg_grid1, 256>>>((const float4*)feat_col, ptr1, edges, agg1, NROW);
    cudaStreamWaitEvent((cudaStream_t)0, evW, 0);   // weights ready (long since done)
    mlp_tc_kernel<<<g_row, 256, SM_TOTAL>>>(feat_row, agg1, w1_a, w2_a,
                                            b1_c2r, b2_c2r, eps_c2r, hrow, out_row, NROW);

    // ---- join, then pass 2 (gathers from updated h_row via graph2 CSR) ----
    cudaStreamWaitEvent((cudaStream_t)0, evJoin, 0);
    csr_agg_kernel<<<agg_grid2, 256>>>((const float4*)hrow, ptr2, edges, agg2, NCOL);
    mlp_tc_kernel<<<g_col, 256, SM_TOTAL>>>(feat_col, agg2, w1_b, w2_b,
                                            b1_r2c, b2_r2c, eps_r2c, nullptr, out_col, NCOL);
}